// round 13
// baseline (speedup 1.0000x reference)
#include <cuda_runtime.h>
#include <math.h>

#define B_   64
#define NI_  2048
#define DI_  8
#define NC_  32
#define DC_  16

#define ICU  16          // i's per front block
#define BTU  8           // b's per front block (chunk = 2 block-columns)
#define NIC  (NI_/ICU)   // 128 i-chunks
#define CHR  32          // i-chunks per b in route
#define CHB  16          // b's per pipeline chunk (u-chunk = 64 MB, L2-resident)

// u layout: [b][i][d4][c][4] -> float4 index = (b*NI+i)*128 + d4*32 + c
__device__ __align__(16) float g_u[B_*NI_*DC_*NC_];        // 256 MB
__device__ __align__(16) float g_s1p[NIC*B_*NC_*DC_];      // s1 slab [ic][b][c][d]
__device__ __align__(16) float g_s1[B_*NC_*DC_];           // reduced s1
__device__ __align__(16) float g_s2[B_*NC_*DC_];
__device__ __align__(16) float g_s3[B_*NC_*DC_];
// s2/s3 zero at load; k_out re-zeroes them each call (replay-safe).

// ---- packed fp32x2 helpers (FFMA2 is PTX-only) ----
__device__ __forceinline__ unsigned long long packf2(float lo, float hi) {
    unsigned long long r;
    asm("mov.b64 %0, {%1, %2};" : "=l"(r)
        : "r"(__float_as_uint(lo)), "r"(__float_as_uint(hi)));
    return r;
}
__device__ __forceinline__ void unpackf2(float& lo, float& hi, unsigned long long v) {
    unsigned int a, b;
    asm("mov.b64 {%0, %1}, %2;" : "=r"(a), "=r"(b) : "l"(v));
    lo = __uint_as_float(a); hi = __uint_as_float(b);
}
__device__ __forceinline__ unsigned long long fmaf2(unsigned long long a,
                                                    unsigned long long b,
                                                    unsigned long long c) {
    unsigned long long r;
    asm("fma.rn.f32x2 %0, %1, %2, %3;" : "=l"(r) : "l"(a), "l"(b), "l"(c));
    return r;
}
__device__ __forceinline__ unsigned long long addf2(unsigned long long a,
                                                    unsigned long long b) {
    unsigned long long r;
    asm("add.rn.f32x2 %0, %1, %2;" : "=l"(r) : "l"(a), "l"(b));
    return r;
}

// XOR-swizzled W_sh index: conflict-free for transpose store and lane=c read.
__device__ __forceinline__ int ws(int df, int c) {
    return df * 32 + (c ^ ((df >> 2) & 31));
}

// ---------------------------------------------------------------------------
// k_front: u materialization (STG.128) + s1 slab partials, for one b-chunk.
// grid (NIC, CHB/BTU) = (128, 2), 256 threads.
// Warp w -> d-quad d4 = w&3, b-half bh = w>>2 (4 b's each). Lane = c.
// ---------------------------------------------------------------------------
__global__ __launch_bounds__(256) void k_front(const float* __restrict__ x,
                                               const float* __restrict__ W,
                                               int b0base) {
    __shared__ __align__(16) float W_sh[2][4096];
    __shared__ __align__(16) float x_sh[1024];      // [il][bl*8 + f], 8 b

    const int t = threadIdx.x, w = t >> 5, c = t & 31;
    const int ic = blockIdx.x;
    const int i0 = ic * ICU;
    const int b0 = b0base + blockIdx.y * BTU;
    const float4* __restrict__ W4 = (const float4*)W;
    const float4* __restrict__ x4 = (const float4*)x;

    // stage x tile: 8 b x 128 floats = 256 float4, one per thread
    {
        const int bl = t >> 5, q = t & 31;
        const float4 v = x4[((b0 + bl) * NI_ + i0) * 2 + q];
        const int il = q >> 1, f0 = (q & 1) * 4;
        x_sh[il * 64 + bl * 8 + f0 + 0] = v.x;
        x_sh[il * 64 + bl * 8 + f0 + 1] = v.y;
        x_sh[il * 64 + bl * 8 + f0 + 2] = v.z;
        x_sh[il * 64 + bl * 8 + f0 + 3] = v.w;
    }
    // stage W for il=0 into buffer 0
    #pragma unroll
    for (int q = 0; q < 4; q++) {
        const int cw = w * 4 + q;
        const float4 v = W4[(cw * NI_ + i0) * 32 + c];
        W_sh[0][ws(4 * c + 0, cw)] = v.x;
        W_sh[0][ws(4 * c + 1, cw)] = v.y;
        W_sh[0][ws(4 * c + 2, cw)] = v.z;
        W_sh[0][ws(4 * c + 3, cw)] = v.w;
    }
    __syncthreads();

    const int d4 = w & 3, bh = w >> 2, db = d4 * 4;
    unsigned long long s1P[4][2];   // per local-b: (d0,d1),(d2,d3) packed
    #pragma unroll
    for (int p = 0; p < 4; p++) { s1P[p][0] = 0ull; s1P[p][1] = 0ull; }

    float4* __restrict__ u4 = (float4*)g_u;
    int buf = 0;

    for (int il = 0; il < ICU; il++) {
        const int i = i0 + il;
        if (il + 1 < ICU) {
            #pragma unroll
            for (int q = 0; q < 4; q++) {
                const int cw = w * 4 + q;
                const float4 v = W4[(cw * NI_ + (i + 1)) * 32 + c];
                W_sh[buf ^ 1][ws(4 * c + 0, cw)] = v.x;
                W_sh[buf ^ 1][ws(4 * c + 1, cw)] = v.y;
                W_sh[buf ^ 1][ws(4 * c + 2, cw)] = v.z;
                W_sh[buf ^ 1][ws(4 * c + 3, cw)] = v.w;
            }
        }
        unsigned long long Wp0[8], Wp1[8];
        #pragma unroll
        for (int f = 0; f < 8; f++) {
            Wp0[f] = packf2(W_sh[buf][ws((db + 0) * 8 + f, c)],
                            W_sh[buf][ws((db + 1) * 8 + f, c)]);
            Wp1[f] = packf2(W_sh[buf][ws((db + 2) * 8 + f, c)],
                            W_sh[buf][ws((db + 3) * 8 + f, c)]);
        }
        #pragma unroll
        for (int bl = 0; bl < 4; bl++) {
            const int blb = bh * 4 + bl;
            const int b = b0 + blb;
            const float4 xa = *(const float4*)&x_sh[il * 64 + blb * 8];
            const float4 xb = *(const float4*)&x_sh[il * 64 + blb * 8 + 4];
            const unsigned long long x0 = packf2(xa.x, xa.x);
            const unsigned long long x1 = packf2(xa.y, xa.y);
            const unsigned long long x2 = packf2(xa.z, xa.z);
            const unsigned long long x3 = packf2(xa.w, xa.w);
            const unsigned long long x4p = packf2(xb.x, xb.x);
            const unsigned long long x5 = packf2(xb.y, xb.y);
            const unsigned long long x6 = packf2(xb.z, xb.z);
            const unsigned long long x7 = packf2(xb.w, xb.w);
            unsigned long long a01 = 0ull, a23 = 0ull;
            a01 = fmaf2(Wp0[0], x0, a01);  a23 = fmaf2(Wp1[0], x0, a23);
            a01 = fmaf2(Wp0[1], x1, a01);  a23 = fmaf2(Wp1[1], x1, a23);
            a01 = fmaf2(Wp0[2], x2, a01);  a23 = fmaf2(Wp1[2], x2, a23);
            a01 = fmaf2(Wp0[3], x3, a01);  a23 = fmaf2(Wp1[3], x3, a23);
            a01 = fmaf2(Wp0[4], x4p, a01); a23 = fmaf2(Wp1[4], x4p, a23);
            a01 = fmaf2(Wp0[5], x5, a01);  a23 = fmaf2(Wp1[5], x5, a23);
            a01 = fmaf2(Wp0[6], x6, a01);  a23 = fmaf2(Wp1[6], x6, a23);
            a01 = fmaf2(Wp0[7], x7, a01);  a23 = fmaf2(Wp1[7], x7, a23);
            s1P[bl][0] = addf2(s1P[bl][0], a01);
            s1P[bl][1] = addf2(s1P[bl][1], a23);
            float u0, u1, u2, u3;
            unpackf2(u0, u1, a01);
            unpackf2(u2, u3, a23);
            u4[(b * NI_ + i) * 128 + d4 * 32 + c] = make_float4(u0, u1, u2, u3);
        }
        __syncthreads();
        buf ^= 1;
    }

    float4* __restrict__ sp4 = (float4*)g_s1p;
    #pragma unroll
    for (int bl = 0; bl < 4; bl++) {
        const int b = b0 + bh * 4 + bl;
        float v0, v1, v2, v3;
        unpackf2(v0, v1, s1P[bl][0]);
        unpackf2(v2, v3, s1P[bl][1]);
        sp4[ic * 8192 + (b * 32 + c) * 4 + d4] = make_float4(v0, v1, v2, v3);
    }
}

// ---------------------------------------------------------------------------
// k_red: fold the slab for one b-chunk: g_s1[off+t] = sum_ic slab[ic][off+t].
// grid 32 x 256 = 8192 threads (CHB*NC*DC).
// ---------------------------------------------------------------------------
__global__ void k_red(int b0base) {
    const int t = blockIdx.x * blockDim.x + threadIdx.x;   // 0..8191
    const int off = b0base * (NC_ * DC_) + t;
    float a0 = 0.0f, a1 = 0.0f, a2 = 0.0f, a3 = 0.0f;
    #pragma unroll 4
    for (int ic = 0; ic < NIC; ic += 4) {
        a0 += g_s1p[(ic + 0) * 32768 + off];
        a1 += g_s1p[(ic + 1) * 32768 + off];
        a2 += g_s1p[(ic + 2) * 32768 + off];
        a3 += g_s1p[(ic + 3) * 32768 + off];
    }
    g_s1[off] = (a0 + a1) + (a2 + a3);
}

// ---------------------------------------------------------------------------
// k_route<PASS> (R12 structure + chunk offset):
//   PASS 2: vr = squash(s1/NC);              s2 += softmax(NI*<u,vr>) * u
//   PASS 3: vr = squash(s1/NC)+squash(s2);   s3 += softmax(NI*<u,vr>) * u
// grid (CHR, CHB), 256 threads, 4 CTAs/SM.
// ---------------------------------------------------------------------------
template <int PASS>
__global__ __launch_bounds__(256, 4) void k_route(int b0base) {
    __shared__ float s_sh[8 * 512];
    const int chunk = blockIdx.x;            // 0..CHR-1
    const int b     = b0base + blockIdx.y;   // chunk b's
    const int w = threadIdx.x >> 5, c = threadIdx.x & 31;
    const int IPW = NI_ / CHR / 8;           // 8
    const int i0 = chunk * (NI_ / CHR) + w * IPW;

    float vr[DC_];
    {   // v1 = squash(s1 / NC)
        const float4* p1 = (const float4*)(g_s1 + (b * NC_ + c) * DC_);
        float sv[DC_]; float sq = 0.0f;
        #pragma unroll
        for (int q = 0; q < 4; q++) {
            const float4 v = p1[q];
            sv[4*q+0] = v.x * (1.0f/NC_); sv[4*q+1] = v.y * (1.0f/NC_);
            sv[4*q+2] = v.z * (1.0f/NC_); sv[4*q+3] = v.w * (1.0f/NC_);
        }
        #pragma unroll
        for (int d = 0; d < DC_; d++) sq += sv[d] * sv[d];
        const float f2 = (sq / (1.0f + sq)) * rsqrtf(sq + 1e-7f);
        #pragma unroll
        for (int d = 0; d < DC_; d++) vr[d] = sv[d] * f2;
    }
    if (PASS == 3) {   // vr += squash(s2)
        const float4* p2 = (const float4*)(g_s2 + (b * NC_ + c) * DC_);
        float sv[DC_]; float sq = 0.0f;
        #pragma unroll
        for (int q = 0; q < 4; q++) {
            const float4 v = p2[q];
            sv[4*q+0] = v.x; sv[4*q+1] = v.y; sv[4*q+2] = v.z; sv[4*q+3] = v.w;
        }
        #pragma unroll
        for (int d = 0; d < DC_; d++) sq += sv[d] * sv[d];
        const float f2 = (sq / (1.0f + sq)) * rsqrtf(sq + 1e-7f);
        #pragma unroll
        for (int d = 0; d < DC_; d++) vr[d] += sv[d] * f2;
    }
    const float4 vr0 = make_float4(vr[0],  vr[1],  vr[2],  vr[3]);
    const float4 vr1 = make_float4(vr[4],  vr[5],  vr[6],  vr[7]);
    const float4 vr2 = make_float4(vr[8],  vr[9],  vr[10], vr[11]);
    const float4 vr3 = make_float4(vr[12], vr[13], vr[14], vr[15]);

    float4 s0 = {0,0,0,0}, s1 = {0,0,0,0}, s2 = {0,0,0,0}, s3 = {0,0,0,0};
    const float4* __restrict__ u4 = (const float4*)g_u;

    #pragma unroll 2
    for (int ii = 0; ii < IPW; ii++) {
        const int base = (b * NI_ + (i0 + ii)) * 128 + c;
        const float4 u0 = u4[base];
        const float4 u1 = u4[base + 32];
        const float4 u2 = u4[base + 64];
        const float4 u3 = u4[base + 96];

        float a = u0.x*vr0.x + u0.y*vr0.y + u0.z*vr0.z + u0.w*vr0.w
                + u1.x*vr1.x + u1.y*vr1.y + u1.z*vr1.z + u1.w*vr1.w
                + u2.x*vr2.x + u2.y*vr2.y + u2.z*vr2.z + u2.w*vr2.w
                + u3.x*vr3.x + u3.y*vr3.y + u3.z*vr3.z + u3.w*vr3.w;
        const float logit = (float)NI_ * a;

        float m = logit;
        #pragma unroll
        for (int off = 16; off > 0; off >>= 1)
            m = fmaxf(m, __shfl_xor_sync(0xFFFFFFFFu, m, off));
        const float e = __expf(logit - m);
        float ssum = e;
        #pragma unroll
        for (int off = 16; off > 0; off >>= 1)
            ssum += __shfl_xor_sync(0xFFFFFFFFu, ssum, off);
        const float coef = e / ssum;

        s0.x = fmaf(coef, u0.x, s0.x); s0.y = fmaf(coef, u0.y, s0.y);
        s0.z = fmaf(coef, u0.z, s0.z); s0.w = fmaf(coef, u0.w, s0.w);
        s1.x = fmaf(coef, u1.x, s1.x); s1.y = fmaf(coef, u1.y, s1.y);
        s1.z = fmaf(coef, u1.z, s1.z); s1.w = fmaf(coef, u1.w, s1.w);
        s2.x = fmaf(coef, u2.x, s2.x); s2.y = fmaf(coef, u2.y, s2.y);
        s2.z = fmaf(coef, u2.z, s2.z); s2.w = fmaf(coef, u2.w, s2.w);
        s3.x = fmaf(coef, u3.x, s3.x); s3.y = fmaf(coef, u3.y, s3.y);
        s3.z = fmaf(coef, u3.z, s3.z); s3.w = fmaf(coef, u3.w, s3.w);
    }

    const int sb = w * 512;
    s_sh[sb +  0*32 + c] = s0.x; s_sh[sb +  1*32 + c] = s0.y;
    s_sh[sb +  2*32 + c] = s0.z; s_sh[sb +  3*32 + c] = s0.w;
    s_sh[sb +  4*32 + c] = s1.x; s_sh[sb +  5*32 + c] = s1.y;
    s_sh[sb +  6*32 + c] = s1.z; s_sh[sb +  7*32 + c] = s1.w;
    s_sh[sb +  8*32 + c] = s2.x; s_sh[sb +  9*32 + c] = s2.y;
    s_sh[sb + 10*32 + c] = s2.z; s_sh[sb + 11*32 + c] = s2.w;
    s_sh[sb + 12*32 + c] = s3.x; s_sh[sb + 13*32 + c] = s3.y;
    s_sh[sb + 14*32 + c] = s3.z; s_sh[sb + 15*32 + c] = s3.w;
    __syncthreads();

    float* gs = (PASS == 2) ? g_s2 : g_s3;
    #pragma unroll
    for (int r = 0; r < 2; r++) {
        const int idx = threadIdx.x + r * 256;   // d*32 + c
        float acc = 0.0f;
        #pragma unroll
        for (int ww = 0; ww < 8; ww++) acc += s_sh[ww * 512 + idx];
        const int cc = idx & 31, dd = idx >> 5;
        atomicAdd(&gs[(b * NC_ + cc) * DC_ + dd], acc);
    }
}

// ---------------------------------------------------------------------------
// k_out: v3 = squash(s3) -> out; zero s2/s3 for next replay.
// ---------------------------------------------------------------------------
__global__ void k_out(float* __restrict__ out) {
    const int t = blockIdx.x * blockDim.x + threadIdx.x;
    if (t >= B_ * NC_) return;
    float sv[DC_]; float sq = 0.0f;
    const float4* p3 = (const float4*)(g_s3 + t * DC_);
    #pragma unroll
    for (int q = 0; q < 4; q++) {
        const float4 v = p3[q];
        sv[4*q+0] = v.x; sv[4*q+1] = v.y; sv[4*q+2] = v.z; sv[4*q+3] = v.w;
    }
    #pragma unroll
    for (int d = 0; d < DC_; d++) sq += sv[d] * sv[d];
    const float f2 = (sq / (1.0f + sq)) * rsqrtf(sq + 1e-7f);
    #pragma unroll
    for (int d = 0; d < DC_; d++) out[t * DC_ + d] = sv[d] * f2;
    #pragma unroll
    for (int d = 0; d < DC_; d++) {
        g_s2[t * DC_ + d] = 0.0f;
        g_s3[t * DC_ + d] = 0.0f;
    }
}

// ---------------------------------------------------------------------------
extern "C" void kernel_launch(void* const* d_in, const int* in_sizes, int n_in,
                              void* d_out, int out_size) {
    const float* x = (const float*)d_in[0];
    const float* W = (const float*)d_in[1];
    if (n_in >= 2 && in_sizes[0] == NC_ * NI_ * DC_ * DI_) {  // defensive order swap
        const float* tmp = x; x = W; W = tmp;
    }
    float* out = (float*)d_out;

    // Per-b-chunk pipeline: u[chunk] (64 MB) stays L2-resident across
    // front -> route2 -> route3, so route reads are L2 hits, not DRAM.
    for (int ch = 0; ch < B_ / CHB; ch++) {
        const int b0 = ch * CHB;
        k_front<<<dim3(NIC, CHB / BTU), 256>>>(x, W, b0);   // u + s1 slab
        k_red<<<(CHB * NC_ * DC_) / 256, 256>>>(b0);        // slab -> g_s1
        k_route<2><<<dim3(CHR, CHB), 256>>>(b0);            // s2
        k_route<3><<<dim3(CHR, CHB), 256>>>(b0);            // s3 (ch0 profiled)
    }
    k_out<<<(B_ * NC_ + 255) / 256, 256>>>(out);            // squash -> out
}

// round 15
// speedup vs baseline: 1.0762x; 1.0762x over previous
#include <cuda_runtime.h>
#include <math.h>

#define B_   64
#define NI_  2048
#define DI_  8
#define NC_  32
#define DC_  16

#define ICU  16          // i's per front block
#define BTU  16          // b's per front block
#define NIC  (NI_/ICU)   // 128 i-chunks
#define CHR  32          // i-chunks per b in route

// u layout: [b][i][d4][c][4] -> float4 index = (b*NI+i)*128 + d4*32 + c
__device__ __align__(16) float g_u[B_*NI_*DC_*NC_];        // 256 MB
__device__ __align__(16) float g_s1p[NIC*B_*NC_*DC_];      // s1 slab [ic][b][c][d]
__device__ __align__(16) float g_s1[B_*NC_*DC_];           // reduced s1
__device__ __align__(16) float g_s2[B_*NC_*DC_];
__device__ __align__(16) float g_s3[B_*NC_*DC_];
// s2/s3 zero at load; k_out re-zeroes them each call (replay-safe).

// ---- packed fp32x2 helpers (FFMA2 is PTX-only) ----
__device__ __forceinline__ unsigned long long packf2(float lo, float hi) {
    unsigned long long r;
    asm("mov.b64 %0, {%1, %2};" : "=l"(r)
        : "r"(__float_as_uint(lo)), "r"(__float_as_uint(hi)));
    return r;
}
__device__ __forceinline__ void unpackf2(float& lo, float& hi, unsigned long long v) {
    unsigned int a, b;
    asm("mov.b64 {%0, %1}, %2;" : "=r"(a), "=r"(b) : "l"(v));
    lo = __uint_as_float(a); hi = __uint_as_float(b);
}
__device__ __forceinline__ unsigned long long fmaf2(unsigned long long a,
                                                    unsigned long long b,
                                                    unsigned long long c) {
    unsigned long long r;
    asm("fma.rn.f32x2 %0, %1, %2, %3;" : "=l"(r) : "l"(a), "l"(b), "l"(c));
    return r;
}
__device__ __forceinline__ unsigned long long addf2(unsigned long long a,
                                                    unsigned long long b) {
    unsigned long long r;
    asm("add.rn.f32x2 %0, %1, %2;" : "=l"(r) : "l"(a), "l"(b));
    return r;
}

// XOR-swizzled W_sh index: conflict-free for transpose store and lane=c read.
__device__ __forceinline__ int ws(int df, int c) {
    return df * 32 + (c ^ ((df >> 2) & 31));
}

// ---------------------------------------------------------------------------
// k_front: u materialization (STG.128) + s1 slab partials (no atomics).
// grid (NIC, B_/BTU) = (128, 4), 256 threads.
// Warp w -> d-quad d4 = w&3, b-half bh = w>>2 (8 b's each). Lane = c.
// b-loop unroll limited to 2: stores need issue slots, not MLP, so shallow
// unroll trims register pressure (target: natural regs <= 85 -> 3 CTAs/SM).
// ---------------------------------------------------------------------------
__global__ __launch_bounds__(256) void k_front(const float* __restrict__ x,
                                               const float* __restrict__ W) {
    __shared__ __align__(16) float W_sh[2][4096];
    __shared__ __align__(16) float x_sh[2048];

    const int t = threadIdx.x, w = t >> 5, c = t & 31;
    const int ic = blockIdx.x;
    const int i0 = ic * ICU;
    const int b0 = blockIdx.y * BTU;
    const float4* __restrict__ W4 = (const float4*)W;
    const float4* __restrict__ x4 = (const float4*)x;

    #pragma unroll
    for (int r = 0; r < 2; r++) {
        const int lin = t + 256 * r;
        const int bl = lin >> 5, q = lin & 31;
        const float4 v = x4[((b0 + bl) * NI_ + i0) * 2 + q];
        const int il = q >> 1, f0 = (q & 1) * 4;
        x_sh[il * 128 + bl * 8 + f0 + 0] = v.x;
        x_sh[il * 128 + bl * 8 + f0 + 1] = v.y;
        x_sh[il * 128 + bl * 8 + f0 + 2] = v.z;
        x_sh[il * 128 + bl * 8 + f0 + 3] = v.w;
    }
    #pragma unroll
    for (int q = 0; q < 4; q++) {
        const int cw = w * 4 + q;
        const float4 v = W4[(cw * NI_ + i0) * 32 + c];
        W_sh[0][ws(4 * c + 0, cw)] = v.x;
        W_sh[0][ws(4 * c + 1, cw)] = v.y;
        W_sh[0][ws(4 * c + 2, cw)] = v.z;
        W_sh[0][ws(4 * c + 3, cw)] = v.w;
    }
    __syncthreads();

    const int d4 = w & 3, bh = w >> 2, db = d4 * 4;
    unsigned long long s1P[8][2];
    #pragma unroll
    for (int p = 0; p < 8; p++) { s1P[p][0] = 0ull; s1P[p][1] = 0ull; }

    float4* __restrict__ u4 = (float4*)g_u;
    int buf = 0;

    for (int il = 0; il < ICU; il++) {
        const int i = i0 + il;
        if (il + 1 < ICU) {
            #pragma unroll
            for (int q = 0; q < 4; q++) {
                const int cw = w * 4 + q;
                const float4 v = W4[(cw * NI_ + (i + 1)) * 32 + c];
                W_sh[buf ^ 1][ws(4 * c + 0, cw)] = v.x;
                W_sh[buf ^ 1][ws(4 * c + 1, cw)] = v.y;
                W_sh[buf ^ 1][ws(4 * c + 2, cw)] = v.z;
                W_sh[buf ^ 1][ws(4 * c + 3, cw)] = v.w;
            }
        }
        unsigned long long Wp0[8], Wp1[8];
        #pragma unroll
        for (int f = 0; f < 8; f++) {
            Wp0[f] = packf2(W_sh[buf][ws((db + 0) * 8 + f, c)],
                            W_sh[buf][ws((db + 1) * 8 + f, c)]);
            Wp1[f] = packf2(W_sh[buf][ws((db + 2) * 8 + f, c)],
                            W_sh[buf][ws((db + 3) * 8 + f, c)]);
        }
        #pragma unroll 2
        for (int bl = 0; bl < 8; bl++) {
            const int b = b0 + bh * 8 + bl;
            const float4 xa = *(const float4*)&x_sh[il * 128 + (bh * 8 + bl) * 8];
            const float4 xb = *(const float4*)&x_sh[il * 128 + (bh * 8 + bl) * 8 + 4];
            const unsigned long long x0 = packf2(xa.x, xa.x);
            const unsigned long long x1 = packf2(xa.y, xa.y);
            const unsigned long long x2 = packf2(xa.z, xa.z);
            const unsigned long long x3 = packf2(xa.w, xa.w);
            const unsigned long long x4p = packf2(xb.x, xb.x);
            const unsigned long long x5 = packf2(xb.y, xb.y);
            const unsigned long long x6 = packf2(xb.z, xb.z);
            const unsigned long long x7 = packf2(xb.w, xb.w);
            unsigned long long a01 = 0ull, a23 = 0ull;
            a01 = fmaf2(Wp0[0], x0, a01);  a23 = fmaf2(Wp1[0], x0, a23);
            a01 = fmaf2(Wp0[1], x1, a01);  a23 = fmaf2(Wp1[1], x1, a23);
            a01 = fmaf2(Wp0[2], x2, a01);  a23 = fmaf2(Wp1[2], x2, a23);
            a01 = fmaf2(Wp0[3], x3, a01);  a23 = fmaf2(Wp1[3], x3, a23);
            a01 = fmaf2(Wp0[4], x4p, a01); a23 = fmaf2(Wp1[4], x4p, a23);
            a01 = fmaf2(Wp0[5], x5, a01);  a23 = fmaf2(Wp1[5], x5, a23);
            a01 = fmaf2(Wp0[6], x6, a01);  a23 = fmaf2(Wp1[6], x6, a23);
            a01 = fmaf2(Wp0[7], x7, a01);  a23 = fmaf2(Wp1[7], x7, a23);
            s1P[bl][0] = addf2(s1P[bl][0], a01);
            s1P[bl][1] = addf2(s1P[bl][1], a23);
            float u0, u1, u2, u3;
            unpackf2(u0, u1, a01);
            unpackf2(u2, u3, a23);
            u4[(b * NI_ + i) * 128 + d4 * 32 + c] = make_float4(u0, u1, u2, u3);
        }
        __syncthreads();
        buf ^= 1;
    }

    float4* __restrict__ sp4 = (float4*)g_s1p;
    #pragma unroll
    for (int bl = 0; bl < 8; bl++) {
        const int b = b0 + bh * 8 + bl;
        float v0, v1, v2, v3;
        unpackf2(v0, v1, s1P[bl][0]);
        unpackf2(v2, v3, s1P[bl][1]);
        sp4[ic * 8192 + (b * 32 + c) * 4 + d4] = make_float4(v0, v1, v2, v3);
    }
}

// ---------------------------------------------------------------------------
// k_red: g_s1[t] = sum over 128 i-chunk slabs.
// ---------------------------------------------------------------------------
__global__ void k_red() {
    const int t = blockIdx.x * blockDim.x + threadIdx.x;
    float a0 = 0.0f, a1 = 0.0f, a2 = 0.0f, a3 = 0.0f;
    #pragma unroll 4
    for (int ic = 0; ic < NIC; ic += 4) {
        a0 += g_s1p[(ic + 0) * 32768 + t];
        a1 += g_s1p[(ic + 1) * 32768 + t];
        a2 += g_s1p[(ic + 2) * 32768 + t];
        a3 += g_s1p[(ic + 3) * 32768 + t];
    }
    g_s1[t] = (a0 + a1) + (a2 + a3);
}

// ---------------------------------------------------------------------------
// k_route<PASS> (R12-verbatim, CHR=32, 4 CTAs/SM):
//   PASS 2: vr = squash(s1/NC);              s2 += softmax(NI*<u,vr>) * u
//   PASS 3: vr = squash(s1/NC)+squash(s2);   s3 += softmax(NI*<u,vr>) * u
// ---------------------------------------------------------------------------
template <int PASS>
__global__ __launch_bounds__(256, 4) void k_route() {
    __shared__ float s_sh[8 * 512];
    const int chunk = blockIdx.x;     // 0..CHR-1
    const int b     = blockIdx.y;     // 0..63
    const int w = threadIdx.x >> 5, c = threadIdx.x & 31;
    const int IPW = NI_ / CHR / 8;    // 8
    const int i0 = chunk * (NI_ / CHR) + w * IPW;

    float vr[DC_];
    {   // v1 = squash(s1 / NC)
        const float4* p1 = (const float4*)(g_s1 + (b * NC_ + c) * DC_);
        float sv[DC_]; float sq = 0.0f;
        #pragma unroll
        for (int q = 0; q < 4; q++) {
            const float4 v = p1[q];
            sv[4*q+0] = v.x * (1.0f/NC_); sv[4*q+1] = v.y * (1.0f/NC_);
            sv[4*q+2] = v.z * (1.0f/NC_); sv[4*q+3] = v.w * (1.0f/NC_);
        }
        #pragma unroll
        for (int d = 0; d < DC_; d++) sq += sv[d] * sv[d];
        const float f2 = (sq / (1.0f + sq)) * rsqrtf(sq + 1e-7f);
        #pragma unroll
        for (int d = 0; d < DC_; d++) vr[d] = sv[d] * f2;
    }
    if (PASS == 3) {   // vr += squash(s2)
        const float4* p2 = (const float4*)(g_s2 + (b * NC_ + c) * DC_);
        float sv[DC_]; float sq = 0.0f;
        #pragma unroll
        for (int q = 0; q < 4; q++) {
            const float4 v = p2[q];
            sv[4*q+0] = v.x; sv[4*q+1] = v.y; sv[4*q+2] = v.z; sv[4*q+3] = v.w;
        }
        #pragma unroll
        for (int d = 0; d < DC_; d++) sq += sv[d] * sv[d];
        const float f2 = (sq / (1.0f + sq)) * rsqrtf(sq + 1e-7f);
        #pragma unroll
        for (int d = 0; d < DC_; d++) vr[d] += sv[d] * f2;
    }
    const float4 vr0 = make_float4(vr[0],  vr[1],  vr[2],  vr[3]);
    const float4 vr1 = make_float4(vr[4],  vr[5],  vr[6],  vr[7]);
    const float4 vr2 = make_float4(vr[8],  vr[9],  vr[10], vr[11]);
    const float4 vr3 = make_float4(vr[12], vr[13], vr[14], vr[15]);

    float4 s0 = {0,0,0,0}, s1 = {0,0,0,0}, s2 = {0,0,0,0}, s3 = {0,0,0,0};
    const float4* __restrict__ u4 = (const float4*)g_u;

    #pragma unroll 2
    for (int ii = 0; ii < IPW; ii++) {
        const int base = (b * NI_ + (i0 + ii)) * 128 + c;
        const float4 u0 = u4[base];
        const float4 u1 = u4[base + 32];
        const float4 u2 = u4[base + 64];
        const float4 u3 = u4[base + 96];

        float a = u0.x*vr0.x + u0.y*vr0.y + u0.z*vr0.z + u0.w*vr0.w
                + u1.x*vr1.x + u1.y*vr1.y + u1.z*vr1.z + u1.w*vr1.w
                + u2.x*vr2.x + u2.y*vr2.y + u2.z*vr2.z + u2.w*vr2.w
                + u3.x*vr3.x + u3.y*vr3.y + u3.z*vr3.z + u3.w*vr3.w;
        const float logit = (float)NI_ * a;

        float m = logit;
        #pragma unroll
        for (int off = 16; off > 0; off >>= 1)
            m = fmaxf(m, __shfl_xor_sync(0xFFFFFFFFu, m, off));
        const float e = __expf(logit - m);
        float ssum = e;
        #pragma unroll
        for (int off = 16; off > 0; off >>= 1)
            ssum += __shfl_xor_sync(0xFFFFFFFFu, ssum, off);
        const float coef = e / ssum;

        s0.x = fmaf(coef, u0.x, s0.x); s0.y = fmaf(coef, u0.y, s0.y);
        s0.z = fmaf(coef, u0.z, s0.z); s0.w = fmaf(coef, u0.w, s0.w);
        s1.x = fmaf(coef, u1.x, s1.x); s1.y = fmaf(coef, u1.y, s1.y);
        s1.z = fmaf(coef, u1.z, s1.z); s1.w = fmaf(coef, u1.w, s1.w);
        s2.x = fmaf(coef, u2.x, s2.x); s2.y = fmaf(coef, u2.y, s2.y);
        s2.z = fmaf(coef, u2.z, s2.z); s2.w = fmaf(coef, u2.w, s2.w);
        s3.x = fmaf(coef, u3.x, s3.x); s3.y = fmaf(coef, u3.y, s3.y);
        s3.z = fmaf(coef, u3.z, s3.z); s3.w = fmaf(coef, u3.w, s3.w);
    }

    const int sb = w * 512;
    s_sh[sb +  0*32 + c] = s0.x; s_sh[sb +  1*32 + c] = s0.y;
    s_sh[sb +  2*32 + c] = s0.z; s_sh[sb +  3*32 + c] = s0.w;
    s_sh[sb +  4*32 + c] = s1.x; s_sh[sb +  5*32 + c] = s1.y;
    s_sh[sb +  6*32 + c] = s1.z; s_sh[sb +  7*32 + c] = s1.w;
    s_sh[sb +  8*32 + c] = s2.x; s_sh[sb +  9*32 + c] = s2.y;
    s_sh[sb + 10*32 + c] = s2.z; s_sh[sb + 11*32 + c] = s2.w;
    s_sh[sb + 12*32 + c] = s3.x; s_sh[sb + 13*32 + c] = s3.y;
    s_sh[sb + 14*32 + c] = s3.z; s_sh[sb + 15*32 + c] = s3.w;
    __syncthreads();

    float* gs = (PASS == 2) ? g_s2 : g_s3;
    #pragma unroll
    for (int r = 0; r < 2; r++) {
        const int idx = threadIdx.x + r * 256;   // d*32 + c
        float acc = 0.0f;
        #pragma unroll
        for (int ww = 0; ww < 8; ww++) acc += s_sh[ww * 512 + idx];
        const int cc = idx & 31, dd = idx >> 5;
        atomicAdd(&gs[(b * NC_ + cc) * DC_ + dd], acc);
    }
}

// ---------------------------------------------------------------------------
// k_out: v3 = squash(s3) -> out; zero s2/s3 for next replay.
// ---------------------------------------------------------------------------
__global__ void k_out(float* __restrict__ out) {
    const int t = blockIdx.x * blockDim.x + threadIdx.x;
    if (t >= B_ * NC_) return;
    float sv[DC_]; float sq = 0.0f;
    const float4* p3 = (const float4*)(g_s3 + t * DC_);
    #pragma unroll
    for (int q = 0; q < 4; q++) {
        const float4 v = p3[q];
        sv[4*q+0] = v.x; sv[4*q+1] = v.y; sv[4*q+2] = v.z; sv[4*q+3] = v.w;
    }
    #pragma unroll
    for (int d = 0; d < DC_; d++) sq += sv[d] * sv[d];
    const float f2 = (sq / (1.0f + sq)) * rsqrtf(sq + 1e-7f);
    #pragma unroll
    for (int d = 0; d < DC_; d++) out[t * DC_ + d] = sv[d] * f2;
    #pragma unroll
    for (int d = 0; d < DC_; d++) {
        g_s2[t * DC_ + d] = 0.0f;
        g_s3[t * DC_ + d] = 0.0f;
    }
}

// ---------------------------------------------------------------------------
extern "C" void kernel_launch(void* const* d_in, const int* in_sizes, int n_in,
                              void* d_out, int out_size) {
    const float* x = (const float*)d_in[0];
    const float* W = (const float*)d_in[1];
    if (n_in >= 2 && in_sizes[0] == NC_ * NI_ * DC_ * DI_) {  // defensive order swap
        const float* tmp = x; x = W; W = tmp;
    }
    float* out = (float*)d_out;

    k_front<<<dim3(NIC, B_ / BTU), 256>>>(x, W);      // #0: u + s1 slab
    k_red<<<128, 256>>>();                            // #1: fold slab -> g_s1
    k_route<2><<<dim3(CHR, B_), 256>>>();             // #2: s2
    k_route<3><<<dim3(CHR, B_), 256>>>();             // #3: s3   (profiled)
    k_out<<<(B_ * NC_ + 255) / 256, 256>>>(out);      // #4: squash -> out
}

// round 17
// speedup vs baseline: 1.2271x; 1.1402x over previous
#include <cuda_runtime.h>
#include <math.h>

#define B_   64
#define NI_  2048
#define DI_  8
#define NC_  32
#define DC_  16

#define ICU  16          // i's per front block
#define BTU  16          // b's per front block
#define NIC  (NI_/ICU)   // 128 i-chunks
#define CHR  32          // i-chunks per b in route

// u layout: [b][i][d4][c][4] -> float4 index = (b*NI+i)*128 + d4*32 + c
__device__ __align__(16) float g_u[B_*NI_*DC_*NC_];        // 256 MB
__device__ __align__(16) float g_s1p[NIC*B_*NC_*DC_];      // s1 slab [ic][b][c][d]
__device__ __align__(16) float g_s1[B_*NC_*DC_];           // reduced s1
__device__ __align__(16) float g_s2[B_*NC_*DC_];
__device__ __align__(16) float g_s3[B_*NC_*DC_];
// s2/s3 zero at load; k_out re-zeroes them each call (replay-safe).

// ---- packed fp32x2 helpers (FFMA2 is PTX-only) ----
__device__ __forceinline__ unsigned long long packf2(float lo, float hi) {
    unsigned long long r;
    asm("mov.b64 %0, {%1, %2};" : "=l"(r)
        : "r"(__float_as_uint(lo)), "r"(__float_as_uint(hi)));
    return r;
}
__device__ __forceinline__ void unpackf2(float& lo, float& hi, unsigned long long v) {
    unsigned int a, b;
    asm("mov.b64 {%0, %1}, %2;" : "=r"(a), "=r"(b) : "l"(v));
    lo = __uint_as_float(a); hi = __uint_as_float(b);
}
__device__ __forceinline__ unsigned long long fmaf2(unsigned long long a,
                                                    unsigned long long b,
                                                    unsigned long long c) {
    unsigned long long r;
    asm("fma.rn.f32x2 %0, %1, %2, %3;" : "=l"(r) : "l"(a), "l"(b), "l"(c));
    return r;
}
__device__ __forceinline__ unsigned long long addf2(unsigned long long a,
                                                    unsigned long long b) {
    unsigned long long r;
    asm("add.rn.f32x2 %0, %1, %2;" : "=l"(r) : "l"(a), "l"(b));
    return r;
}

// XOR-swizzled W_sh index: conflict-free for transpose store and lane=c read.
__device__ __forceinline__ int ws(int df, int c) {
    return df * 32 + (c ^ ((df >> 2) & 31));
}

// ---------------------------------------------------------------------------
// k_front (R12 structure): u materialization + s1 slab partials (no atomics).
// grid (NIC, B_/BTU) = (128, 4), 256 threads.
// Warp w -> d-quad d4 = w&3, b-half bh = w>>2 (8 b's each). Lane = c.
// u stores use __stcs (evict-first): u cannot be L2-retained anyway, and the
// hint keeps the 32 MB W working set resident across the 4 b-block-columns.
// ---------------------------------------------------------------------------
__global__ __launch_bounds__(256) void k_front(const float* __restrict__ x,
                                               const float* __restrict__ W) {
    __shared__ __align__(16) float W_sh[2][4096];
    __shared__ __align__(16) float x_sh[2048];

    const int t = threadIdx.x, w = t >> 5, c = t & 31;
    const int ic = blockIdx.x;
    const int i0 = ic * ICU;
    const int b0 = blockIdx.y * BTU;
    const float4* __restrict__ W4 = (const float4*)W;
    const float4* __restrict__ x4 = (const float4*)x;

    #pragma unroll
    for (int r = 0; r < 2; r++) {
        const int lin = t + 256 * r;
        const int bl = lin >> 5, q = lin & 31;
        const float4 v = x4[((b0 + bl) * NI_ + i0) * 2 + q];
        const int il = q >> 1, f0 = (q & 1) * 4;
        x_sh[il * 128 + bl * 8 + f0 + 0] = v.x;
        x_sh[il * 128 + bl * 8 + f0 + 1] = v.y;
        x_sh[il * 128 + bl * 8 + f0 + 2] = v.z;
        x_sh[il * 128 + bl * 8 + f0 + 3] = v.w;
    }
    #pragma unroll
    for (int q = 0; q < 4; q++) {
        const int cw = w * 4 + q;
        const float4 v = W4[(cw * NI_ + i0) * 32 + c];
        W_sh[0][ws(4 * c + 0, cw)] = v.x;
        W_sh[0][ws(4 * c + 1, cw)] = v.y;
        W_sh[0][ws(4 * c + 2, cw)] = v.z;
        W_sh[0][ws(4 * c + 3, cw)] = v.w;
    }
    __syncthreads();

    const int d4 = w & 3, bh = w >> 2, db = d4 * 4;
    unsigned long long s1P[8][2];
    #pragma unroll
    for (int p = 0; p < 8; p++) { s1P[p][0] = 0ull; s1P[p][1] = 0ull; }

    float4* __restrict__ u4 = (float4*)g_u;
    int buf = 0;

    for (int il = 0; il < ICU; il++) {
        const int i = i0 + il;
        if (il + 1 < ICU) {
            #pragma unroll
            for (int q = 0; q < 4; q++) {
                const int cw = w * 4 + q;
                const float4 v = W4[(cw * NI_ + (i + 1)) * 32 + c];
                W_sh[buf ^ 1][ws(4 * c + 0, cw)] = v.x;
                W_sh[buf ^ 1][ws(4 * c + 1, cw)] = v.y;
                W_sh[buf ^ 1][ws(4 * c + 2, cw)] = v.z;
                W_sh[buf ^ 1][ws(4 * c + 3, cw)] = v.w;
            }
        }
        unsigned long long Wp0[8], Wp1[8];
        #pragma unroll
        for (int f = 0; f < 8; f++) {
            Wp0[f] = packf2(W_sh[buf][ws((db + 0) * 8 + f, c)],
                            W_sh[buf][ws((db + 1) * 8 + f, c)]);
            Wp1[f] = packf2(W_sh[buf][ws((db + 2) * 8 + f, c)],
                            W_sh[buf][ws((db + 3) * 8 + f, c)]);
        }
        #pragma unroll
        for (int bl = 0; bl < 8; bl++) {
            const int b = b0 + bh * 8 + bl;
            const float4 xa = *(const float4*)&x_sh[il * 128 + (bh * 8 + bl) * 8];
            const float4 xb = *(const float4*)&x_sh[il * 128 + (bh * 8 + bl) * 8 + 4];
            const unsigned long long x0 = packf2(xa.x, xa.x);
            const unsigned long long x1 = packf2(xa.y, xa.y);
            const unsigned long long x2 = packf2(xa.z, xa.z);
            const unsigned long long x3 = packf2(xa.w, xa.w);
            const unsigned long long x4p = packf2(xb.x, xb.x);
            const unsigned long long x5 = packf2(xb.y, xb.y);
            const unsigned long long x6 = packf2(xb.z, xb.z);
            const unsigned long long x7 = packf2(xb.w, xb.w);
            unsigned long long a01 = 0ull, a23 = 0ull;
            a01 = fmaf2(Wp0[0], x0, a01);  a23 = fmaf2(Wp1[0], x0, a23);
            a01 = fmaf2(Wp0[1], x1, a01);  a23 = fmaf2(Wp1[1], x1, a23);
            a01 = fmaf2(Wp0[2], x2, a01);  a23 = fmaf2(Wp1[2], x2, a23);
            a01 = fmaf2(Wp0[3], x3, a01);  a23 = fmaf2(Wp1[3], x3, a23);
            a01 = fmaf2(Wp0[4], x4p, a01); a23 = fmaf2(Wp1[4], x4p, a23);
            a01 = fmaf2(Wp0[5], x5, a01);  a23 = fmaf2(Wp1[5], x5, a23);
            a01 = fmaf2(Wp0[6], x6, a01);  a23 = fmaf2(Wp1[6], x6, a23);
            a01 = fmaf2(Wp0[7], x7, a01);  a23 = fmaf2(Wp1[7], x7, a23);
            s1P[bl][0] = addf2(s1P[bl][0], a01);
            s1P[bl][1] = addf2(s1P[bl][1], a23);
            float u0, u1, u2, u3;
            unpackf2(u0, u1, a01);
            unpackf2(u2, u3, a23);
            __stcs(&u4[(b * NI_ + i) * 128 + d4 * 32 + c],
                   make_float4(u0, u1, u2, u3));   // evict-first: protect W in L2
        }
        __syncthreads();
        buf ^= 1;
    }

    float4* __restrict__ sp4 = (float4*)g_s1p;
    #pragma unroll
    for (int bl = 0; bl < 8; bl++) {
        const int b = b0 + bh * 8 + bl;
        float v0, v1, v2, v3;
        unpackf2(v0, v1, s1P[bl][0]);
        unpackf2(v2, v3, s1P[bl][1]);
        sp4[ic * 8192 + (b * 32 + c) * 4 + d4] = make_float4(v0, v1, v2, v3);
    }
}

// ---------------------------------------------------------------------------
// k_red: g_s1[t] = sum over 128 i-chunk slabs.
// ---------------------------------------------------------------------------
__global__ void k_red() {
    const int t = blockIdx.x * blockDim.x + threadIdx.x;
    float a0 = 0.0f, a1 = 0.0f, a2 = 0.0f, a3 = 0.0f;
    #pragma unroll 4
    for (int ic = 0; ic < NIC; ic += 4) {
        a0 += g_s1p[(ic + 0) * 32768 + t];
        a1 += g_s1p[(ic + 1) * 32768 + t];
        a2 += g_s1p[(ic + 2) * 32768 + t];
        a3 += g_s1p[(ic + 3) * 32768 + t];
    }
    g_s1[t] = (a0 + a1) + (a2 + a3);
}

// ---------------------------------------------------------------------------
// k_route<PASS> (R12-verbatim, CHR=32, 4 CTAs/SM):
//   PASS 2: vr = squash(s1/NC);              s2 += softmax(NI*<u,vr>) * u
//   PASS 3: vr = squash(s1/NC)+squash(s2);   s3 += softmax(NI*<u,vr>) * u
// ---------------------------------------------------------------------------
template <int PASS>
__global__ __launch_bounds__(256, 4) void k_route() {
    __shared__ float s_sh[8 * 512];
    const int chunk = blockIdx.x;     // 0..CHR-1
    const int b     = blockIdx.y;     // 0..63
    const int w = threadIdx.x >> 5, c = threadIdx.x & 31;
    const int IPW = NI_ / CHR / 8;    // 8
    const int i0 = chunk * (NI_ / CHR) + w * IPW;

    float vr[DC_];
    {   // v1 = squash(s1 / NC)
        const float4* p1 = (const float4*)(g_s1 + (b * NC_ + c) * DC_);
        float sv[DC_]; float sq = 0.0f;
        #pragma unroll
        for (int q = 0; q < 4; q++) {
            const float4 v = p1[q];
            sv[4*q+0] = v.x * (1.0f/NC_); sv[4*q+1] = v.y * (1.0f/NC_);
            sv[4*q+2] = v.z * (1.0f/NC_); sv[4*q+3] = v.w * (1.0f/NC_);
        }
        #pragma unroll
        for (int d = 0; d < DC_; d++) sq += sv[d] * sv[d];
        const float f2 = (sq / (1.0f + sq)) * rsqrtf(sq + 1e-7f);
        #pragma unroll
        for (int d = 0; d < DC_; d++) vr[d] = sv[d] * f2;
    }
    if (PASS == 3) {   // vr += squash(s2)
        const float4* p2 = (const float4*)(g_s2 + (b * NC_ + c) * DC_);
        float sv[DC_]; float sq = 0.0f;
        #pragma unroll
        for (int q = 0; q < 4; q++) {
            const float4 v = p2[q];
            sv[4*q+0] = v.x; sv[4*q+1] = v.y; sv[4*q+2] = v.z; sv[4*q+3] = v.w;
        }
        #pragma unroll
        for (int d = 0; d < DC_; d++) sq += sv[d] * sv[d];
        const float f2 = (sq / (1.0f + sq)) * rsqrtf(sq + 1e-7f);
        #pragma unroll
        for (int d = 0; d < DC_; d++) vr[d] += sv[d] * f2;
    }
    const float4 vr0 = make_float4(vr[0],  vr[1],  vr[2],  vr[3]);
    const float4 vr1 = make_float4(vr[4],  vr[5],  vr[6],  vr[7]);
    const float4 vr2 = make_float4(vr[8],  vr[9],  vr[10], vr[11]);
    const float4 vr3 = make_float4(vr[12], vr[13], vr[14], vr[15]);

    float4 s0 = {0,0,0,0}, s1 = {0,0,0,0}, s2 = {0,0,0,0}, s3 = {0,0,0,0};
    const float4* __restrict__ u4 = (const float4*)g_u;

    #pragma unroll 2
    for (int ii = 0; ii < IPW; ii++) {
        const int base = (b * NI_ + (i0 + ii)) * 128 + c;
        const float4 u0 = u4[base];
        const float4 u1 = u4[base + 32];
        const float4 u2 = u4[base + 64];
        const float4 u3 = u4[base + 96];

        float a = u0.x*vr0.x + u0.y*vr0.y + u0.z*vr0.z + u0.w*vr0.w
                + u1.x*vr1.x + u1.y*vr1.y + u1.z*vr1.z + u1.w*vr1.w
                + u2.x*vr2.x + u2.y*vr2.y + u2.z*vr2.z + u2.w*vr2.w
                + u3.x*vr3.x + u3.y*vr3.y + u3.z*vr3.z + u3.w*vr3.w;
        const float logit = (float)NI_ * a;

        float m = logit;
        #pragma unroll
        for (int off = 16; off > 0; off >>= 1)
            m = fmaxf(m, __shfl_xor_sync(0xFFFFFFFFu, m, off));
        const float e = __expf(logit - m);
        float ssum = e;
        #pragma unroll
        for (int off = 16; off > 0; off >>= 1)
            ssum += __shfl_xor_sync(0xFFFFFFFFu, ssum, off);
        const float coef = e / ssum;

        s0.x = fmaf(coef, u0.x, s0.x); s0.y = fmaf(coef, u0.y, s0.y);
        s0.z = fmaf(coef, u0.z, s0.z); s0.w = fmaf(coef, u0.w, s0.w);
        s1.x = fmaf(coef, u1.x, s1.x); s1.y = fmaf(coef, u1.y, s1.y);
        s1.z = fmaf(coef, u1.z, s1.z); s1.w = fmaf(coef, u1.w, s1.w);
        s2.x = fmaf(coef, u2.x, s2.x); s2.y = fmaf(coef, u2.y, s2.y);
        s2.z = fmaf(coef, u2.z, s2.z); s2.w = fmaf(coef, u2.w, s2.w);
        s3.x = fmaf(coef, u3.x, s3.x); s3.y = fmaf(coef, u3.y, s3.y);
        s3.z = fmaf(coef, u3.z, s3.z); s3.w = fmaf(coef, u3.w, s3.w);
    }

    const int sb = w * 512;
    s_sh[sb +  0*32 + c] = s0.x; s_sh[sb +  1*32 + c] = s0.y;
    s_sh[sb +  2*32 + c] = s0.z; s_sh[sb +  3*32 + c] = s0.w;
    s_sh[sb +  4*32 + c] = s1.x; s_sh[sb +  5*32 + c] = s1.y;
    s_sh[sb +  6*32 + c] = s1.z; s_sh[sb +  7*32 + c] = s1.w;
    s_sh[sb +  8*32 + c] = s2.x; s_sh[sb +  9*32 + c] = s2.y;
    s_sh[sb + 10*32 + c] = s2.z; s_sh[sb + 11*32 + c] = s2.w;
    s_sh[sb + 12*32 + c] = s3.x; s_sh[sb + 13*32 + c] = s3.y;
    s_sh[sb + 14*32 + c] = s3.z; s_sh[sb + 15*32 + c] = s3.w;
    __syncthreads();

    float* gs = (PASS == 2) ? g_s2 : g_s3;
    #pragma unroll
    for (int r = 0; r < 2; r++) {
        const int idx = threadIdx.x + r * 256;   // d*32 + c
        float acc = 0.0f;
        #pragma unroll
        for (int ww = 0; ww < 8; ww++) acc += s_sh[ww * 512 + idx];
        const int cc = idx & 31, dd = idx >> 5;
        atomicAdd(&gs[(b * NC_ + cc) * DC_ + dd], acc);
    }
}

// ---------------------------------------------------------------------------
// k_out: v3 = squash(s3) -> out; zero s2/s3 for next replay.
// ---------------------------------------------------------------------------
__global__ void k_out(float* __restrict__ out) {
    const int t = blockIdx.x * blockDim.x + threadIdx.x;
    if (t >= B_ * NC_) return;
    float sv[DC_]; float sq = 0.0f;
    const float4* p3 = (const float4*)(g_s3 + t * DC_);
    #pragma unroll
    for (int q = 0; q < 4; q++) {
        const float4 v = p3[q];
        sv[4*q+0] = v.x; sv[4*q+1] = v.y; sv[4*q+2] = v.z; sv[4*q+3] = v.w;
    }
    #pragma unroll
    for (int d = 0; d < DC_; d++) sq += sv[d] * sv[d];
    const float f2 = (sq / (1.0f + sq)) * rsqrtf(sq + 1e-7f);
    #pragma unroll
    for (int d = 0; d < DC_; d++) out[t * DC_ + d] = sv[d] * f2;
    #pragma unroll
    for (int d = 0; d < DC_; d++) {
        g_s2[t * DC_ + d] = 0.0f;
        g_s3[t * DC_ + d] = 0.0f;
    }
}

// ---------------------------------------------------------------------------
extern "C" void kernel_launch(void* const* d_in, const int* in_sizes, int n_in,
                              void* d_out, int out_size) {
    const float* x = (const float*)d_in[0];
    const float* W = (const float*)d_in[1];
    if (n_in >= 2 && in_sizes[0] == NC_ * NI_ * DC_ * DI_) {  // defensive order swap
        const float* tmp = x; x = W; W = tmp;
    }
    float* out = (float*)d_out;

    k_front<<<dim3(NIC, B_ / BTU), 256>>>(x, W);      // #0: u + s1 slab
    k_red<<<128, 256>>>();                            // #1: fold slab -> g_s1
    k_route<2><<<dim3(CHR, B_), 256>>>();             // #2: s2
    k_route<3><<<dim3(CHR, B_), 256>>>();             // #3: s3   (profiled)
    k_out<<<(B_ * NC_ + 255) / 256, 256>>>(out);      // #4: squash -> out
}